// round 12
// baseline (speedup 1.0000x reference)
#include <cuda_runtime.h>
#include <cuda_bf16.h>
#include <cstdint>

// Cross-batch attention == one flat head: N=8192, D=128.
// mma.sync bf16 split-hi/lo (3 passes), static softmax shift (exact),
// Q fragments in registers, 3-stage KV ring, PV(t-1) overlapped with
// softmax(t), split-K=2 + combine.

#define N_TOK   8192
#define DIM     128
#define BR      128
#define BC      64
#define THREADS 256
#define NT      64            // 4096 keys per CTA / 64
#define LOG2E   1.4426950408889634f
#define SMB     115.41560327111707f   // 80*log2(e)

#define PK_B 272      // K/Q row: 256B data + 16B pad
#define PV_B 144      // V^T row: 128B data + 16B pad

// stage layout (bytes): KH | KL | VH | VL
#define STAGE_B 71680
#define BKL 17408
#define BVH 34816
#define BVL 53248
#define SM_KV 0
#define SMEM_BYTES (3 * STAGE_B)      // 215040

// ---- device scratch ----
static __device__ __align__(16) __nv_bfloat16 g_Qh[N_TOK * DIM];
static __device__ __align__(16) __nv_bfloat16 g_Ql[N_TOK * DIM];
static __device__ __align__(16) __nv_bfloat16 g_Kh[N_TOK * DIM];
static __device__ __align__(16) __nv_bfloat16 g_Kl[N_TOK * DIM];
static __device__ __align__(16) __nv_bfloat16 g_Vth[DIM * N_TOK];   // [d][key]
static __device__ __align__(16) __nv_bfloat16 g_Vtl[DIM * N_TOK];
static __device__ float g_Op[2 * N_TOK * DIM];
static __device__ float g_lp[2 * N_TOK];

__device__ __forceinline__ uint32_t packh(float a, float b) {
    __nv_bfloat162 h = __floats2bfloat162_rn(a, b);
    return *reinterpret_cast<uint32_t*>(&h);
}
__device__ __forceinline__ void split2(float a, float b, uint32_t& hi, uint32_t& lo) {
    float ah = __bfloat162float(__float2bfloat16_rn(a));
    float bh = __bfloat162float(__float2bfloat16_rn(b));
    hi = packh(ah, bh);
    lo = packh(a - ah, b - bh);
}
__device__ __forceinline__ float ex2(float x) {
    float r; asm("ex2.approx.ftz.f32 %0, %1;" : "=f"(r) : "f"(x)); return r;
}

// ---- prep kernels ----
__global__ void conv_qk_kernel(const float* __restrict__ Q, const float* __restrict__ K)
{
    size_t i = (size_t)blockIdx.x * blockDim.x + threadIdx.x;
    const float4* src = reinterpret_cast<const float4*>(blockIdx.y == 0 ? Q : K);
    uint32_t* dh = reinterpret_cast<uint32_t*>(blockIdx.y == 0 ? g_Qh : g_Kh);
    uint32_t* dl = reinterpret_cast<uint32_t*>(blockIdx.y == 0 ? g_Ql : g_Kl);
    float4 v = src[i];
    uint32_t h0, l0, h1, l1;
    split2(v.x, v.y, h0, l0);
    split2(v.z, v.w, h1, l1);
    dh[2 * i] = h0; dh[2 * i + 1] = h1;
    dl[2 * i] = l0; dl[2 * i + 1] = l1;
}

__global__ void conv_v_kernel(const float* __restrict__ V)
{
    int key0 = blockIdx.x * 64;
    int kp = threadIdx.x & 31;
    int d0 = threadIdx.x >> 5;
    uint32_t* oh = reinterpret_cast<uint32_t*>(g_Vth);
    uint32_t* ol = reinterpret_cast<uint32_t*>(g_Vtl);
#pragma unroll
    for (int dd = 0; dd < 16; dd++) {
        int d = d0 * 16 + dd;
        float a = V[(size_t)(key0 + 2 * kp) * DIM + d];
        float b = V[(size_t)(key0 + 2 * kp + 1) * DIM + d];
        uint32_t h, l;
        split2(a, b, h, l);
        size_t w = (size_t)d * (N_TOK / 2) + (key0 >> 1) + kp;
        oh[w] = h; ol[w] = l;
    }
}

// ---- async helpers ----
__device__ __forceinline__ void cpa(uint32_t dst, const void* src) {
    asm volatile("cp.async.cg.shared.global [%0], [%1], 16;\n" :: "r"(dst), "l"(src));
}
#define CP_COMMIT() asm volatile("cp.async.commit_group;\n")
#define CP_WAIT0()  asm volatile("cp.async.wait_group 0;\n")
#define CP_WAIT1()  asm volatile("cp.async.wait_group 1;\n")

__device__ __forceinline__ void ldsm4(uint32_t& r0, uint32_t& r1, uint32_t& r2, uint32_t& r3,
                                      uint32_t addr) {
    asm volatile("ldmatrix.sync.aligned.m8n8.x4.shared.b16 {%0,%1,%2,%3}, [%4];\n"
                 : "=r"(r0), "=r"(r1), "=r"(r2), "=r"(r3) : "r"(addr));
}

__device__ __forceinline__ void mma16816(float* c, const uint32_t* a, const uint32_t* b) {
    asm volatile(
        "mma.sync.aligned.m16n8k16.row.col.f32.bf16.bf16.f32 "
        "{%0,%1,%2,%3}, {%4,%5,%6,%7}, {%8,%9}, {%0,%1,%2,%3};\n"
        : "+f"(c[0]), "+f"(c[1]), "+f"(c[2]), "+f"(c[3])
        : "r"(a[0]), "r"(a[1]), "r"(a[2]), "r"(a[3]), "r"(b[0]), "r"(b[1]));
}

__device__ __forceinline__ void issue_tile(uint32_t sbuf, int key0, int tid)
{
    const char* kh = (const char*)g_Kh + (size_t)key0 * 256;
    const char* kl = (const char*)g_Kl + (size_t)key0 * 256;
    const char* vh = (const char*)g_Vth + (size_t)key0 * 2;
    const char* vl = (const char*)g_Vtl + (size_t)key0 * 2;
#pragma unroll
    for (int it = 0; it < 4; it++) {
        int j = tid + it * THREADS;
        int r = j >> 4, c = j & 15;
        cpa(sbuf + r * PK_B + c * 16, kh + (size_t)r * 256 + c * 16);
        cpa(sbuf + BKL + r * PK_B + c * 16, kl + (size_t)r * 256 + c * 16);
        int d = j >> 3, c2 = j & 7;
        cpa(sbuf + BVH + d * PV_B + c2 * 16, vh + (size_t)d * (N_TOK * 2) + c2 * 16);
        cpa(sbuf + BVL + d * PV_B + c2 * 16, vl + (size_t)d * (N_TOK * 2) + c2 * 16);
    }
}

// PV chunk kk (keys 16*kk..16*kk+15) of tile whose V lives at bV
#define PV_CHUNK(kk, Ph01, Ph23, Pl01, Pl23, bV) do {                         \
    uint32_t ah_[4] = {Ph01[2*(kk)], Ph23[2*(kk)], Ph01[2*(kk)+1], Ph23[2*(kk)+1]}; \
    uint32_t al_[4] = {Pl01[2*(kk)], Pl23[2*(kk)], Pl01[2*(kk)+1], Pl23[2*(kk)+1]}; \
    _Pragma("unroll")                                                         \
    for (int nt2 = 0; nt2 < 8; nt2++) {                                       \
        uint32_t vh_[4], vl_[4];                                              \
        ldsm4(vh_[0], vh_[1], vh_[2], vh_[3], (bV) + nt2 * 16 * PV_B + (kk) * 32 + voff); \
        ldsm4(vl_[0], vl_[1], vl_[2], vl_[3], (bV) + (BVL - BVH) + nt2 * 16 * PV_B + (kk) * 32 + voff); \
        uint32_t b0_[2] = {vh_[0], vh_[2]}, b1_[2] = {vh_[1], vh_[3]};        \
        uint32_t c0_[2] = {vl_[0], vl_[2]}, c1_[2] = {vl_[1], vl_[3]};        \
        mma16816(o[2*nt2],   ah_, b0_);                                       \
        mma16816(o[2*nt2+1], ah_, b1_);                                       \
        mma16816(o[2*nt2],   ah_, c0_);                                       \
        mma16816(o[2*nt2+1], ah_, c1_);                                       \
        mma16816(o[2*nt2],   al_, b0_);                                       \
        mma16816(o[2*nt2+1], al_, b1_);                                       \
    }                                                                         \
} while (0)

// one pipeline step: QK(T), then softmax(T)->C set overlapped with PV(T-1) from P set
#define BODY(T, Ch01, Ch23, Cl01, Cl23, Ph01, Ph23, Pl01, Pl23) do {          \
    const int t_ = (T);                                                       \
    if (t_ >= NT - 2) { CP_WAIT0(); } else { CP_WAIT1(); }                    \
    __syncthreads();                                                          \
    const uint32_t bK_ = sb + SM_KV + (t_ % 3) * STAGE_B;                     \
    float s[8][4];                                                            \
    _Pragma("unroll")                                                         \
    for (int nt = 0; nt < 8; nt++)                                            \
        { s[nt][0] = 0.f; s[nt][1] = 0.f; s[nt][2] = 0.f; s[nt][3] = 0.f; }   \
    _Pragma("unroll")                                                         \
    for (int kc = 0; kc < 8; kc++) {                                          \
        _Pragma("unroll")                                                     \
        for (int nt2 = 0; nt2 < 4; nt2++) {                                   \
            uint32_t kh_[4], kl_[4];                                          \
            ldsm4(kh_[0], kh_[1], kh_[2], kh_[3], bK_ + nt2 * 16 * PK_B + kc * 32 + koff); \
            ldsm4(kl_[0], kl_[1], kl_[2], kl_[3], bK_ + BKL + nt2 * 16 * PK_B + kc * 32 + koff); \
            uint32_t b0_[2] = {kh_[0], kh_[2]}, b1_[2] = {kh_[1], kh_[3]};    \
            uint32_t c0_[2] = {kl_[0], kl_[2]}, c1_[2] = {kl_[1], kl_[3]};    \
            mma16816(s[2*nt2],   qfh[kc], b0_);                               \
            mma16816(s[2*nt2+1], qfh[kc], b1_);                               \
            mma16816(s[2*nt2],   qfh[kc], c0_);                               \
            mma16816(s[2*nt2+1], qfh[kc], c1_);                               \
            mma16816(s[2*nt2],   qfl[kc], b0_);                               \
            mma16816(s[2*nt2+1], qfl[kc], b1_);                               \
        }                                                                     \
    }                                                                         \
    const uint32_t bV_ = sb + SM_KV + ((t_ + 2) % 3) * STAGE_B + BVH;         \
    _Pragma("unroll")                                                         \
    for (int k = 0; k < 4; k++) {                                             \
        _Pragma("unroll")                                                     \
        for (int u = 0; u < 2; u++) {                                         \
            int nt = 2 * k + u;                                               \
            float p0 = ex2(fmaf(s[nt][0], LOG2E, -SMB));                      \
            float p1 = ex2(fmaf(s[nt][1], LOG2E, -SMB));                      \
            float p2 = ex2(fmaf(s[nt][2], LOG2E, -SMB));                      \
            float p3 = ex2(fmaf(s[nt][3], LOG2E, -SMB));                      \
            l0 += p0 + p1; l1 += p2 + p3;                                     \
            split2(p0, p1, Ch01[nt], Cl01[nt]);                               \
            split2(p2, p3, Ch23[nt], Cl23[nt]);                               \
        }                                                                     \
        if (t_ > 0) PV_CHUNK(k, Ph01, Ph23, Pl01, Pl23, bV_);                 \
    }                                                                         \
    __syncthreads();                                                          \
    if (t_ + 2 < NT)                                                          \
        issue_tile(sb + SM_KV + ((t_ + 2) % 3) * STAGE_B, kb0 + (t_ + 2) * BC, tid); \
    CP_COMMIT();                                                              \
} while (0)

__global__ void __launch_bounds__(THREADS, 1)
attn_main_kernel()
{
    extern __shared__ char sm[];
    const uint32_t sb = (uint32_t)__cvta_generic_to_shared(sm);

    const int tid  = threadIdx.x;
    const int warp = tid >> 5;
    const int lane = tid & 31;
    const int g    = lane >> 2;
    const int t    = lane & 3;
    const int split = blockIdx.x & 1;
    const int qbase = (blockIdx.x >> 1) * BR;
    const int kb0   = split * (NT * BC);
    const int r0 = warp * 16 + g;

    const uint32_t koff = (lane & 15) * PK_B + ((lane >> 4) << 4);
    const uint32_t voff = (lane & 15) * PV_B + ((lane >> 4) << 4);

    // ---- prologue: stage Q in stages 0/1, load frags to regs ----
    {
        const char* qh = (const char*)g_Qh + (size_t)qbase * 256;
        const char* ql = (const char*)g_Ql + (size_t)qbase * 256;
#pragma unroll
        for (int it = 0; it < 8; it++) {
            int j = tid + it * THREADS;
            int r = j >> 4, c = j & 15;      // 128 rows x 16 chunks
            cpa(sb + SM_KV + r * PK_B + c * 16, qh + (size_t)r * 256 + c * 16);
            cpa(sb + SM_KV + STAGE_B + r * PK_B + c * 16, ql + (size_t)r * 256 + c * 16);
        }
        CP_COMMIT();
        CP_WAIT0();
        __syncthreads();
    }
    uint32_t qfh[8][4], qfl[8][4];
#pragma unroll
    for (int kc = 0; kc < 8; kc++) {
        ldsm4(qfh[kc][0], qfh[kc][1], qfh[kc][2], qfh[kc][3],
              sb + SM_KV + warp * 16 * PK_B + kc * 32 + koff);
        ldsm4(qfl[kc][0], qfl[kc][1], qfl[kc][2], qfl[kc][3],
              sb + SM_KV + STAGE_B + warp * 16 * PK_B + kc * 32 + koff);
    }
    __syncthreads();   // Q staging dead; stages may be reused

    issue_tile(sb + SM_KV, kb0, tid);
    CP_COMMIT();
    issue_tile(sb + SM_KV + STAGE_B, kb0 + BC, tid);
    CP_COMMIT();

    float o[16][4];
#pragma unroll
    for (int nt = 0; nt < 16; nt++)
#pragma unroll
        for (int j = 0; j < 4; j++) o[nt][j] = 0.f;
    float l0 = 0.f, l1 = 0.f;

    uint32_t xh01[8], xh23[8], xl01[8], xl23[8];
    uint32_t yh01[8], yh23[8], yl01[8], yl23[8];

    for (int tt = 0; tt < NT; tt += 2) {
        BODY(tt,     xh01, xh23, xl01, xl23, yh01, yh23, yl01, yl23);
        BODY(tt + 1, yh01, yh23, yl01, yl23, xh01, xh23, xl01, xl23);
    }

    // epilogue PV(63): V in stage (63 % 3) = 0, P in y set
    {
        const uint32_t bV_ = sb + SM_KV + 0 * STAGE_B + BVH;
#pragma unroll
        for (int k = 0; k < 4; k++)
            PV_CHUNK(k, yh01, yh23, yl01, yl23, bV_);
    }

    // ---- finalize: reduce row sums, store unnormalized partials ----
    l0 += __shfl_xor_sync(0xffffffffu, l0, 1);
    l0 += __shfl_xor_sync(0xffffffffu, l0, 2);
    l1 += __shfl_xor_sync(0xffffffffu, l1, 1);
    l1 += __shfl_xor_sync(0xffffffffu, l1, 2);

    const size_t rowa = (size_t)(split * N_TOK) + qbase + r0;
    const size_t rowb = rowa + 8;
    if (t == 0) {
        g_lp[rowa] = l0;
        g_lp[rowb] = l1;
    }
#pragma unroll
    for (int nt = 0; nt < 16; nt++) {
        int c = nt * 8 + 2 * t;
        g_Op[rowa * DIM + c]     = o[nt][0];
        g_Op[rowa * DIM + c + 1] = o[nt][1];
        g_Op[rowb * DIM + c]     = o[nt][2];
        g_Op[rowb * DIM + c + 1] = o[nt][3];
    }
}

// ---- combine: Out = (O0 + O1) / (l0 + l1) ----
__global__ void combine_kernel(float* __restrict__ Out)
{
    int i = blockIdx.x * 256 + threadIdx.x;
    int row = i >> 5;
    float inv = 1.f / (g_lp[row] + g_lp[N_TOK + row]);
    const float4* A = reinterpret_cast<const float4*>(g_Op);
    float4 a = A[i];
    float4 c = A[(size_t)N_TOK * (DIM / 4) + i];
    reinterpret_cast<float4*>(Out)[i] =
        make_float4((a.x + c.x) * inv, (a.y + c.y) * inv, (a.z + c.z) * inv, (a.w + c.w) * inv);
}

extern "C" void kernel_launch(void* const* d_in, const int* in_sizes, int n_in,
                              void* d_out, int out_size)
{
    const float* Q = (const float*)d_in[0];
    const float* K = (const float*)d_in[1];
    const float* V = (const float*)d_in[2];
    float* Out = (float*)d_out;
    (void)in_sizes; (void)n_in; (void)out_size;

    conv_qk_kernel<<<dim3((N_TOK * DIM / 4) / 256, 2), 256>>>(Q, K);
    conv_v_kernel<<<N_TOK / 64, 256>>>(V);

    cudaFuncSetAttribute(attn_main_kernel,
                         cudaFuncAttributeMaxDynamicSharedMemorySize, SMEM_BYTES);
    attn_main_kernel<<<(N_TOK / BR) * 2, THREADS, SMEM_BYTES>>>();
    combine_kernel<<<1024, 256>>>(Out);
}

// round 13
// speedup vs baseline: 1.1174x; 1.1174x over previous
#include <cuda_runtime.h>
#include <cuda_bf16.h>
#include <cstdint>

// Cross-batch attention == one flat head: N=8192, D=128.
// mma.sync bf16 split-hi/lo (3 passes), static softmax shift (exact),
// Q in smem, 2-stage KV ring with SPLIT refill (K at iter top, V mid-iter),
// PV(t-1) overlapped with softmax(t), split-K=2 + combine.

#define N_TOK   8192
#define DIM     128
#define BR      128
#define BC      64
#define THREADS 256
#define NT      64            // 4096 keys per CTA / 64
#define LOG2E   1.4426950408889634f
#define SMB     115.41560327111707f   // 80*log2(e)

#define PK_B 272      // K/Q row: 256B data + 16B pad
#define PV_B 144      // V^T row: 128B data + 16B pad

// smem byte offsets
#define SQH 0
#define SQL 34816
#define SBUF0 69632
#define BUFSZ 71680          // KH 17408 | KL 17408 | VH 18432 | VL 18432
#define BKL 17408
#define BVH 34816
#define BVL 53248
#define SMEM_BYTES (SBUF0 + 2*BUFSZ)   // 212992

// ---- device scratch ----
static __device__ __align__(16) __nv_bfloat16 g_Qh[N_TOK * DIM];
static __device__ __align__(16) __nv_bfloat16 g_Ql[N_TOK * DIM];
static __device__ __align__(16) __nv_bfloat16 g_Kh[N_TOK * DIM];
static __device__ __align__(16) __nv_bfloat16 g_Kl[N_TOK * DIM];
static __device__ __align__(16) __nv_bfloat16 g_Vth[DIM * N_TOK];   // [d][key]
static __device__ __align__(16) __nv_bfloat16 g_Vtl[DIM * N_TOK];
static __device__ float g_Op[2 * N_TOK * DIM];
static __device__ float g_lp[2 * N_TOK];

__device__ __forceinline__ uint32_t packh(float a, float b) {
    __nv_bfloat162 h = __floats2bfloat162_rn(a, b);
    return *reinterpret_cast<uint32_t*>(&h);
}
__device__ __forceinline__ void split2(float a, float b, uint32_t& hi, uint32_t& lo) {
    float ah = __bfloat162float(__float2bfloat16_rn(a));
    float bh = __bfloat162float(__float2bfloat16_rn(b));
    hi = packh(ah, bh);
    lo = packh(a - ah, b - bh);
}
__device__ __forceinline__ float ex2(float x) {
    float r; asm("ex2.approx.ftz.f32 %0, %1;" : "=f"(r) : "f"(x)); return r;
}

// ---- prep kernels ----
__global__ void conv_qk_kernel(const float* __restrict__ Q, const float* __restrict__ K)
{
    size_t i = (size_t)blockIdx.x * blockDim.x + threadIdx.x;
    const float4* src = reinterpret_cast<const float4*>(blockIdx.y == 0 ? Q : K);
    uint32_t* dh = reinterpret_cast<uint32_t*>(blockIdx.y == 0 ? g_Qh : g_Kh);
    uint32_t* dl = reinterpret_cast<uint32_t*>(blockIdx.y == 0 ? g_Ql : g_Kl);
    float4 v = src[i];
    uint32_t h0, l0, h1, l1;
    split2(v.x, v.y, h0, l0);
    split2(v.z, v.w, h1, l1);
    dh[2 * i] = h0; dh[2 * i + 1] = h1;
    dl[2 * i] = l0; dl[2 * i + 1] = l1;
}

__global__ void conv_v_kernel(const float* __restrict__ V)
{
    int key0 = blockIdx.x * 64;
    int kp = threadIdx.x & 31;
    int d0 = threadIdx.x >> 5;
    uint32_t* oh = reinterpret_cast<uint32_t*>(g_Vth);
    uint32_t* ol = reinterpret_cast<uint32_t*>(g_Vtl);
#pragma unroll
    for (int dd = 0; dd < 16; dd++) {
        int d = d0 * 16 + dd;
        float a = V[(size_t)(key0 + 2 * kp) * DIM + d];
        float b = V[(size_t)(key0 + 2 * kp + 1) * DIM + d];
        uint32_t h, l;
        split2(a, b, h, l);
        size_t w = (size_t)d * (N_TOK / 2) + (key0 >> 1) + kp;
        oh[w] = h; ol[w] = l;
    }
}

// ---- async helpers ----
__device__ __forceinline__ void cpa(uint32_t dst, const void* src) {
    asm volatile("cp.async.cg.shared.global [%0], [%1], 16;\n" :: "r"(dst), "l"(src));
}
#define CP_COMMIT() asm volatile("cp.async.commit_group;\n")
#define CP_WAIT0()  asm volatile("cp.async.wait_group 0;\n")
#define CP_WAIT1()  asm volatile("cp.async.wait_group 1;\n")

__device__ __forceinline__ void ldsm4(uint32_t& r0, uint32_t& r1, uint32_t& r2, uint32_t& r3,
                                      uint32_t addr) {
    asm volatile("ldmatrix.sync.aligned.m8n8.x4.shared.b16 {%0,%1,%2,%3}, [%4];\n"
                 : "=r"(r0), "=r"(r1), "=r"(r2), "=r"(r3) : "r"(addr));
}

__device__ __forceinline__ void mma16816(float* c, const uint32_t* a, const uint32_t* b) {
    asm volatile(
        "mma.sync.aligned.m16n8k16.row.col.f32.bf16.bf16.f32 "
        "{%0,%1,%2,%3}, {%4,%5,%6,%7}, {%8,%9}, {%0,%1,%2,%3};\n"
        : "+f"(c[0]), "+f"(c[1]), "+f"(c[2]), "+f"(c[3])
        : "r"(a[0]), "r"(a[1]), "r"(a[2]), "r"(a[3]), "r"(b[0]), "r"(b[1]));
}

// K-half of a stage: 8 cp.async per thread
__device__ __forceinline__ void issue_K(uint32_t sbuf, int key0, int tid)
{
    const char* kh = (const char*)g_Kh + (size_t)key0 * 256;
    const char* kl = (const char*)g_Kl + (size_t)key0 * 256;
#pragma unroll
    for (int it = 0; it < 4; it++) {
        int j = tid + it * THREADS;
        int r = j >> 4, c = j & 15;          // 64 rows x 16 chunks
        cpa(sbuf + r * PK_B + c * 16, kh + (size_t)r * 256 + c * 16);
        cpa(sbuf + BKL + r * PK_B + c * 16, kl + (size_t)r * 256 + c * 16);
    }
}
// V-half of a stage: 8 cp.async per thread
__device__ __forceinline__ void issue_V(uint32_t sbuf, int key0, int tid)
{
    const char* vh = (const char*)g_Vth + (size_t)key0 * 2;
    const char* vl = (const char*)g_Vtl + (size_t)key0 * 2;
#pragma unroll
    for (int it = 0; it < 4; it++) {
        int j = tid + it * THREADS;
        int d = j >> 3, c2 = j & 7;          // 128 rows x 8 chunks
        cpa(sbuf + BVH + d * PV_B + c2 * 16, vh + (size_t)d * (N_TOK * 2) + c2 * 16);
        cpa(sbuf + BVL + d * PV_B + c2 * 16, vl + (size_t)d * (N_TOK * 2) + c2 * 16);
    }
}

// PV chunk kk (keys 16*kk..16*kk+15) reading V at bV
#define PV_CHUNK(kk, Ph01, Ph23, Pl01, Pl23, bV) do {                         \
    uint32_t ah_[4] = {Ph01[2*(kk)], Ph23[2*(kk)], Ph01[2*(kk)+1], Ph23[2*(kk)+1]}; \
    uint32_t al_[4] = {Pl01[2*(kk)], Pl23[2*(kk)], Pl01[2*(kk)+1], Pl23[2*(kk)+1]}; \
    _Pragma("unroll")                                                         \
    for (int nt2 = 0; nt2 < 8; nt2++) {                                       \
        uint32_t vh_[4], vl_[4];                                              \
        ldsm4(vh_[0], vh_[1], vh_[2], vh_[3], (bV) + nt2 * 16 * PV_B + (kk) * 32 + voff); \
        ldsm4(vl_[0], vl_[1], vl_[2], vl_[3], (bV) + (BVL - BVH) + nt2 * 16 * PV_B + (kk) * 32 + voff); \
        uint32_t b0_[2] = {vh_[0], vh_[2]}, b1_[2] = {vh_[1], vh_[3]};        \
        uint32_t c0_[2] = {vl_[0], vl_[2]}, c1_[2] = {vl_[1], vl_[3]};        \
        mma16816(o[2*nt2],   ah_, b0_);                                       \
        mma16816(o[2*nt2+1], ah_, b1_);                                       \
        mma16816(o[2*nt2],   ah_, c0_);                                       \
        mma16816(o[2*nt2+1], ah_, c1_);                                       \
        mma16816(o[2*nt2],   al_, b0_);                                       \
        mma16816(o[2*nt2+1], al_, b1_);                                       \
    }                                                                         \
} while (0)

// One pipeline step:
//   wait K(T) landed; issue K(T+1) into freed K-region;
//   QK(T); softmax(T)->C overlapped with PV(T-1) from P + V stage (T-1)&1;
//   sync; issue V(T+1) into freed V-region.
#define BODY(T, Ch01, Ch23, Cl01, Cl23, Ph01, Ph23, Pl01, Pl23, DOPV, DOISS) do { \
    const int t_ = (T);                                                       \
    if (DOPV) { CP_WAIT1(); } else { CP_WAIT0(); }                            \
    __syncthreads();                                                          \
    if (DOISS) { issue_K(sb + SBUF0 + ((t_ + 1) & 1) * BUFSZ, kb0 + (t_ + 1) * BC, tid); \
                 CP_COMMIT(); }                                               \
    const uint32_t bK_ = sb + SBUF0 + (t_ & 1) * BUFSZ;                       \
    float s[8][4];                                                            \
    _Pragma("unroll")                                                         \
    for (int nt = 0; nt < 8; nt++)                                            \
        { s[nt][0] = 0.f; s[nt][1] = 0.f; s[nt][2] = 0.f; s[nt][3] = 0.f; }   \
    _Pragma("unroll")                                                         \
    for (int kc = 0; kc < 8; kc++) {                                          \
        uint32_t qh_[4], ql_[4];                                              \
        ldsm4(qh_[0], qh_[1], qh_[2], qh_[3], sb + SQH + warp * 16 * PK_B + kc * 32 + koff); \
        ldsm4(ql_[0], ql_[1], ql_[2], ql_[3], sb + SQL + warp * 16 * PK_B + kc * 32 + koff); \
        _Pragma("unroll")                                                     \
        for (int nt2 = 0; nt2 < 4; nt2++) {                                   \
            uint32_t kh_[4], kl_[4];                                          \
            ldsm4(kh_[0], kh_[1], kh_[2], kh_[3], bK_ + nt2 * 16 * PK_B + kc * 32 + koff); \
            ldsm4(kl_[0], kl_[1], kl_[2], kl_[3], bK_ + BKL + nt2 * 16 * PK_B + kc * 32 + koff); \
            uint32_t b0_[2] = {kh_[0], kh_[2]}, b1_[2] = {kh_[1], kh_[3]};    \
            uint32_t c0_[2] = {kl_[0], kl_[2]}, c1_[2] = {kl_[1], kl_[3]};    \
            mma16816(s[2*nt2],   qh_, b0_);                                   \
            mma16816(s[2*nt2+1], qh_, b1_);                                   \
            mma16816(s[2*nt2],   qh_, c0_);                                   \
            mma16816(s[2*nt2+1], qh_, c1_);                                   \
            mma16816(s[2*nt2],   ql_, b0_);                                   \
            mma16816(s[2*nt2+1], ql_, b1_);                                   \
        }                                                                     \
    }                                                                         \
    const uint32_t bV_ = sb + SBUF0 + ((t_ + 1) & 1) * BUFSZ + BVH;           \
    _Pragma("unroll")                                                         \
    for (int k = 0; k < 4; k++) {                                             \
        _Pragma("unroll")                                                     \
        for (int u = 0; u < 2; u++) {                                         \
            int nt = 2 * k + u;                                               \
            float p0 = ex2(fmaf(s[nt][0], LOG2E, -SMB));                      \
            float p1 = ex2(fmaf(s[nt][1], LOG2E, -SMB));                      \
            float p2 = ex2(fmaf(s[nt][2], LOG2E, -SMB));                      \
            float p3 = ex2(fmaf(s[nt][3], LOG2E, -SMB));                      \
            l0 += p0 + p1; l1 += p2 + p3;                                     \
            split2(p0, p1, Ch01[nt], Cl01[nt]);                               \
            split2(p2, p3, Ch23[nt], Cl23[nt]);                               \
        }                                                                     \
        if (DOPV) PV_CHUNK(k, Ph01, Ph23, Pl01, Pl23, bV_);                   \
    }                                                                         \
    __syncthreads();                                                          \
    if (DOISS) { issue_V(sb + SBUF0 + ((t_ + 1) & 1) * BUFSZ, kb0 + (t_ + 1) * BC, tid); \
                 CP_COMMIT(); }                                               \
} while (0)

__global__ void __launch_bounds__(THREADS, 1)
attn_main_kernel()
{
    extern __shared__ char sm[];
    const uint32_t sb = (uint32_t)__cvta_generic_to_shared(sm);

    const int tid  = threadIdx.x;
    const int warp = tid >> 5;
    const int lane = tid & 31;
    const int g    = lane >> 2;
    const int t    = lane & 3;
    const int split = blockIdx.x & 1;
    const int qbase = (blockIdx.x >> 1) * BR;
    const int kb0   = split * (NT * BC);
    const int r0 = warp * 16 + g;

    const uint32_t koff = (lane & 15) * PK_B + ((lane >> 4) << 4);
    const uint32_t voff = (lane & 15) * PV_B + ((lane >> 4) << 4);

    // ---- prologue: Q into its smem home; K0+V0 into stage 0 ----
    {
        const char* qh = (const char*)g_Qh + (size_t)qbase * 256;
        const char* ql = (const char*)g_Ql + (size_t)qbase * 256;
#pragma unroll
        for (int it = 0; it < 8; it++) {
            int j = tid + it * THREADS;
            int r = j >> 4, c = j & 15;      // 128 rows x 16 chunks
            cpa(sb + SQH + r * PK_B + c * 16, qh + (size_t)r * 256 + c * 16);
            cpa(sb + SQL + r * PK_B + c * 16, ql + (size_t)r * 256 + c * 16);
        }
        CP_COMMIT();
        issue_K(sb + SBUF0, kb0, tid);
        issue_V(sb + SBUF0, kb0, tid);
        CP_COMMIT();
    }

    float o[16][4];
#pragma unroll
    for (int nt = 0; nt < 16; nt++)
#pragma unroll
        for (int j = 0; j < 4; j++) o[nt][j] = 0.f;
    float l0 = 0.f, l1 = 0.f;

    uint32_t xh01[8], xh23[8], xl01[8], xl23[8];
    uint32_t yh01[8], yh23[8], yl01[8], yl23[8];

    // t=0: waits everything, no PV, issues K1/V1
    BODY(0, xh01, xh23, xl01, xl23, yh01, yh23, yl01, yl23, 0, 1);
    // t=1..62: full steady state (odd t writes y, even t writes x)
    for (int tt = 1; tt < NT - 1; tt += 2) {
        BODY(tt,     yh01, yh23, yl01, yl23, xh01, xh23, xl01, xl23, 1, 1);
        BODY(tt + 1, xh01, xh23, xl01, xl23, yh01, yh23, yl01, yl23, 1, 1);
    }
    // t=63: no issue
    BODY(NT - 1, yh01, yh23, yl01, yl23, xh01, xh23, xl01, xl23, 1, 0);

    // epilogue: PV(63); V(63) lives in stage 1
    CP_WAIT0();
    __syncthreads();
    {
        const uint32_t bV_ = sb + SBUF0 + 1 * BUFSZ + BVH;
#pragma unroll
        for (int k = 0; k < 4; k++)
            PV_CHUNK(k, yh01, yh23, yl01, yl23, bV_);
    }

    // ---- finalize: reduce row sums, store unnormalized partials ----
    l0 += __shfl_xor_sync(0xffffffffu, l0, 1);
    l0 += __shfl_xor_sync(0xffffffffu, l0, 2);
    l1 += __shfl_xor_sync(0xffffffffu, l1, 1);
    l1 += __shfl_xor_sync(0xffffffffu, l1, 2);

    const size_t rowa = (size_t)(split * N_TOK) + qbase + r0;
    const size_t rowb = rowa + 8;
    if (t == 0) {
        g_lp[rowa] = l0;
        g_lp[rowb] = l1;
    }
#pragma unroll
    for (int nt = 0; nt < 16; nt++) {
        int c = nt * 8 + 2 * t;
        g_Op[rowa * DIM + c]     = o[nt][0];
        g_Op[rowa * DIM + c + 1] = o[nt][1];
        g_Op[rowb * DIM + c]     = o[nt][2];
        g_Op[rowb * DIM + c + 1] = o[nt][3];
    }
}

// ---- combine: Out = (O0 + O1) / (l0 + l1) ----
__global__ void combine_kernel(float* __restrict__ Out)
{
    int i = blockIdx.x * 256 + threadIdx.x;
    int row = i >> 5;
    float inv = 1.f / (g_lp[row] + g_lp[N_TOK + row]);
    const float4* A = reinterpret_cast<const float4*>(g_Op);
    float4 a = A[i];
    float4 c = A[(size_t)N_TOK * (DIM / 4) + i];
    reinterpret_cast<float4*>(Out)[i] =
        make_float4((a.x + c.x) * inv, (a.y + c.y) * inv, (a.z + c.z) * inv, (a.w + c.w) * inv);
}

extern "C" void kernel_launch(void* const* d_in, const int* in_sizes, int n_in,
                              void* d_out, int out_size)
{
    const float* Q = (const float*)d_in[0];
    const float* K = (const float*)d_in[1];
    const float* V = (const float*)d_in[2];
    float* Out = (float*)d_out;
    (void)in_sizes; (void)n_in; (void)out_size;

    conv_qk_kernel<<<dim3((N_TOK * DIM / 4) / 256, 2), 256>>>(Q, K);
    conv_v_kernel<<<N_TOK / 64, 256>>>(V);

    cudaFuncSetAttribute(attn_main_kernel,
                         cudaFuncAttributeMaxDynamicSharedMemorySize, SMEM_BYTES);
    attn_main_kernel<<<(N_TOK / BR) * 2, THREADS, SMEM_BYTES>>>();
    combine_kernel<<<1024, 256>>>(Out);
}